// round 15
// baseline (speedup 1.0000x reference)
#include <cuda_runtime.h>
#include <cuda_bf16.h>
#include <cuda_fp16.h>
#include <math.h>
#include <stdint.h>

#define NNODES 50000
#define MPAD   50048      // 391 * 128
#define KD     256
#define HEADS  4
#define EMAX   1700000
#define NPB    4          // nodes per aggregate block (50000 = 4 * 12500)

// ---------------- device scratch --------------------------------------------
__device__ __half2         g_hsH[MPAD * KD / 2]; // source transform (fp16)
__device__ __half2         g_Af[MPAD * KD / 2];  // activations, plain fp16
__device__ __half          g_Bt[3 * KD * KD];    // W^T fp16, all layers
__device__ float           g_as[MPAD * HEADS];
__device__ float           g_ad[NNODES * HEADS];
__device__ float           g_vd[3 * KD * HEADS]; // Wd_l @ att_d_l, [l][k][h]
__device__ int             g_deg[NNODES];
__device__ int             g_rowptr[NNODES + 1];
__device__ int             g_cursor[NNODES];
__device__ int             g_srcs[EMAX];         // CSR-ordered SOURCE ids

// ---------------- helpers ----------------------------------------------------
__device__ __forceinline__ void mma_f16(float* c, const uint32_t* a, const uint32_t* b) {
    asm volatile(
        "mma.sync.aligned.m16n8k16.row.col.f32.f16.f16.f32 "
        "{%0,%1,%2,%3},{%4,%5,%6,%7},{%8,%9},{%0,%1,%2,%3};"
        : "+f"(c[0]), "+f"(c[1]), "+f"(c[2]), "+f"(c[3])
        : "r"(a[0]), "r"(a[1]), "r"(a[2]), "r"(a[3]), "r"(b[0]), "r"(b[1]));
}

__device__ __forceinline__ float4 lrelu_exp4(float4 a, float4 ad) {
    float v; float4 ex;
    v = a.x + ad.x; v = v > 0.f ? v : 0.2f * v; ex.x = __expf(v);
    v = a.y + ad.y; v = v > 0.f ? v : 0.2f * v; ex.y = __expf(v);
    v = a.z + ad.z; v = v > 0.f ? v : 0.2f * v; ex.z = __expf(v);
    v = a.w + ad.w; v = v > 0.f ? v : 0.2f * v; ex.w = __expf(v);
    return ex;
}

#define CP_ASYNC16(dst_u32, src_ptr) \
    asm volatile("cp.async.cg.shared.global [%0], [%1], 16;" \
                 :: "r"(dst_u32), "l"(src_ptr))
#define CP_COMMIT() asm volatile("cp.async.commit_group;" ::: "memory")
#define CP_WAIT0()  asm volatile("cp.async.wait_group 0;" ::: "memory")

// ---------------- CSR build --------------------------------------------------
__global__ void count_deg_kernel(const int* __restrict__ dst, int e2) {
    int e = blockIdx.x * blockDim.x + threadIdx.x;
    if (e < e2) atomicAdd(&g_deg[dst[e]], 1);
}
__global__ void scan_kernel() {
    __shared__ int s[1024];
    int t = threadIdx.x;
    const int per = (NNODES + 1023) / 1024;
    int start = t * per;
    int end = start + per; if (end > NNODES) end = NNODES;
    int sum = 0;
    for (int i = start; i < end; i++) sum += g_deg[i];
    s[t] = sum;
    __syncthreads();
    for (int off = 1; off < 1024; off <<= 1) {
        int v = (t >= off) ? s[t - off] : 0;
        __syncthreads();
        s[t] += v;
        __syncthreads();
    }
    int run = (t > 0) ? s[t - 1] : 0;
    for (int i = start; i < end; i++) {
        int d = g_deg[i];
        g_rowptr[i] = run;
        g_cursor[i] = run;
        run += d;
    }
    if (t == 0) g_rowptr[NNODES] = s[1023];
}
__global__ void scatter_kernel(const int* __restrict__ src,
                               const int* __restrict__ dst, int e2) {
    int e = blockIdx.x * blockDim.x + threadIdx.x;
    if (e < e2) {
        int pos = atomicAdd(&g_cursor[dst[e]], 1);
        g_srcs[pos] = src[e];
    }
}

// ---------------- fused: x -> fp16 AND layer-0 a_d ---------------------------
__global__ void __launch_bounds__(256) prep_x_kernel(const float* __restrict__ X) {
    __shared__ float svd[KD * 4];
    int tid = threadIdx.x;
    for (int i = tid; i < KD * 4; i += 256) svd[i] = g_vd[i];
    __syncthreads();
    int warp = tid >> 5, lane = tid & 31;
    int n = blockIdx.x * 8 + warp;
    if (n >= NNODES) return;
    float a0 = 0.f, a1 = 0.f, a2 = 0.f, a3 = 0.f;
#pragma unroll
    for (int g4 = 0; g4 < 2; g4++) {
        int f4i = n * 64 + lane * 2 + g4;
        float4 xv = ((const float4*)X)[f4i];
        __half2 h01 = __floats2half2_rn(xv.x, xv.y);
        __half2 h23 = __floats2half2_rn(xv.z, xv.w);
        uint2 hp;
        hp.x = *reinterpret_cast<unsigned*>(&h01);
        hp.y = *reinterpret_cast<unsigned*>(&h23);
        ((uint2*)g_Af)[f4i] = hp;
        const float* p = &svd[(lane * 8 + g4 * 4) * 4];
        a0 += xv.x * p[0] + xv.y * p[4] + xv.z * p[8]  + xv.w * p[12];
        a1 += xv.x * p[1] + xv.y * p[5] + xv.z * p[9]  + xv.w * p[13];
        a2 += xv.x * p[2] + xv.y * p[6] + xv.z * p[10] + xv.w * p[14];
        a3 += xv.x * p[3] + xv.y * p[7] + xv.z * p[11] + xv.w * p[15];
    }
#pragma unroll
    for (int off = 16; off > 0; off >>= 1) {
        a0 += __shfl_xor_sync(0xffffffffu, a0, off);
        a1 += __shfl_xor_sync(0xffffffffu, a1, off);
        a2 += __shfl_xor_sync(0xffffffffu, a2, off);
        a3 += __shfl_xor_sync(0xffffffffu, a3, off);
    }
    if (lane == 0) ((float4*)g_ad)[n] = make_float4(a0, a1, a2, a3);
}

// ---------------- B transpose -> fp16, all 3 layers --------------------------
__global__ void btsplit_all_kernel(const float* __restrict__ W0,
                                   const float* __restrict__ W1,
                                   const float* __restrict__ W2) {
    int l = blockIdx.y;
    const float* W = (l == 0) ? W0 : (l == 1) ? W1 : W2;
    int i = blockIdx.x * blockDim.x + threadIdx.x;
    int n = i >> 8, k = i & 255;
    g_Bt[l * KD * KD + i] = __float2half_rn(W[k * KD + n]);
}

// ---------------- vd for all layers in one launch ----------------------------
__global__ void compute_vd_all_kernel(const float* __restrict__ Wd0,
                                      const float* __restrict__ Wd1,
                                      const float* __restrict__ Wd2,
                                      const float* __restrict__ ad0,
                                      const float* __restrict__ ad1,
                                      const float* __restrict__ ad2) {
    int l = blockIdx.x;
    const float* Wd = (l == 0) ? Wd0 : (l == 1) ? Wd1 : Wd2;
    const float* ad = (l == 0) ? ad0 : (l == 1) ? ad1 : ad2;
    int idx = threadIdx.x;
    int k = idx >> 2;
    int h = idx & 3;
    float s = 0.f;
#pragma unroll 8
    for (int c = 0; c < 64; c++) s += Wd[k * KD + h * 64 + c] * ad[h * 64 + c];
    g_vd[l * KD * HEADS + k * 4 + h] = s;
}

// ---------------- GEMM: hs(fp16) = A(fp16) @ B(fp16), single product ---------
#define S32 20
#define STAGE_W 5120
__global__ void __launch_bounds__(256) gemm_mma_kernel(const float* __restrict__ attS,
                                                       const __half* __restrict__ Bh) {
    extern __shared__ uint32_t smem_u[];
    __shared__ float s_as[128][2];
    const int tid = threadIdx.x;
    const int wid = tid >> 5, lane = tid & 31;
    const int wm = wid >> 2, wn = wid & 3;
    const int row0 = blockIdx.x * 128;
    const int n0 = blockIdx.y * 128;
    const int g8 = lane >> 2, tq = lane & 3;
    const uint32_t smem_b = (uint32_t)__cvta_generic_to_shared(smem_u);
    const __half* Af = (const __half*)g_Af;

    ((float*)s_as)[tid] = 0.f;

    const int lr0 = tid >> 2;
    const int lc4 = tid & 3;
    float c[4][4][4];
#pragma unroll
    for (int mt = 0; mt < 4; mt++)
#pragma unroll
        for (int nt = 0; nt < 4; nt++)
#pragma unroll
            for (int j = 0; j < 4; j++) c[mt][nt][j] = 0.f;

#define LOAD_CHUNK(stg, cc) do {                                               \
    int k0 = (cc) * 32;                                                        \
    _Pragma("unroll")                                                          \
    for (int i = 0; i < 2; i++) {                                              \
        int r = lr0 + i * 64;                                                  \
        long ga = (long)(row0 + r) * KD + k0 + lc4 * 8;                        \
        long gb = (long)(n0 + r) * KD + k0 + lc4 * 8;                          \
        uint32_t so = smem_b + ((stg) * STAGE_W + r * S32 + lc4 * 4) * 4;      \
        CP_ASYNC16(so,            Af + ga);                                    \
        CP_ASYNC16(so + 2560 * 4, Bh + gb);                                    \
    }                                                                          \
} while (0)

    LOAD_CHUNK(0, 0);
    CP_COMMIT();

    for (int cch = 0; cch < 8; cch++) {
        const int stg = cch & 1;
        CP_WAIT0();
        __syncthreads();
        if (cch < 7) { LOAD_CHUNK(stg ^ 1, cch + 1); CP_COMMIT(); }
        const uint32_t* sA  = smem_u + stg * STAGE_W;
        const uint32_t* sBh = sA + 2560;
#pragma unroll
        for (int kk = 0; kk < 2; kk++) {
            const int kb = kk * 8;
            uint32_t ah[4][4], bh[4][2];
#pragma unroll
            for (int mt = 0; mt < 4; mt++) {
                int r = (wm * 64 + mt * 16 + g8) * S32 + kb + tq;
                int r8 = r + 8 * S32;
                ah[mt][0] = sA[r];     ah[mt][1] = sA[r8];
                ah[mt][2] = sA[r + 4]; ah[mt][3] = sA[r8 + 4];
            }
#pragma unroll
            for (int nt = 0; nt < 4; nt++) {
                int r = (wn * 32 + nt * 8 + g8) * S32 + kb + tq;
                bh[nt][0] = sBh[r]; bh[nt][1] = sBh[r + 4];
            }
#pragma unroll
            for (int mt = 0; mt < 4; mt++)
#pragma unroll
                for (int nt = 0; nt < 4; nt++)
                    mma_f16(c[mt][nt], ah[mt], bh[nt]);
        }
        __syncthreads();
    }

    // epilogue 1: fragments -> g_hsH (fp16)
#pragma unroll
    for (int mt = 0; mt < 4; mt++) {
        int r = row0 + wm * 64 + mt * 16 + g8;
#pragma unroll
        for (int nt = 0; nt < 4; nt++) {
            int h2i = 64 * blockIdx.y + wn * 16 + nt * 4 + tq;
            g_hsH[(long)r * 128 + h2i]       = __floats2half2_rn(c[mt][nt][0], c[mt][nt][1]);
            g_hsH[(long)(r + 8) * 128 + h2i] = __floats2half2_rn(c[mt][nt][2], c[mt][nt][3]);
        }
    }
    // epilogue 2: fused a_s via block-shared reduction
    {
        float p0[4] = {0.f, 0.f, 0.f, 0.f};
        float p1[4] = {0.f, 0.f, 0.f, 0.f};
#pragma unroll
        for (int nt = 0; nt < 4; nt++) {
            int col = n0 + wn * 32 + nt * 8 + tq * 2;
            float a0 = attS[col], a1 = attS[col + 1];
#pragma unroll
            for (int mt = 0; mt < 4; mt++) {
                p0[mt] += c[mt][nt][0] * a0 + c[mt][nt][1] * a1;
                p1[mt] += c[mt][nt][2] * a0 + c[mt][nt][3] * a1;
            }
        }
        int hl = wn >> 1;
#pragma unroll
        for (int mt = 0; mt < 4; mt++) {
            p0[mt] += __shfl_xor_sync(0xffffffffu, p0[mt], 1);
            p0[mt] += __shfl_xor_sync(0xffffffffu, p0[mt], 2);
            p1[mt] += __shfl_xor_sync(0xffffffffu, p1[mt], 1);
            p1[mt] += __shfl_xor_sync(0xffffffffu, p1[mt], 2);
            if (tq == 0) {
                int rl = wm * 64 + mt * 16 + g8;
                atomicAdd(&s_as[rl][hl], p0[mt]);
                atomicAdd(&s_as[rl + 8][hl], p1[mt]);
            }
        }
        __syncthreads();
        int rl = tid >> 1, h2 = tid & 1;
        g_as[(row0 + rl) * 4 + blockIdx.y * 2 + h2] = s_as[rl][h2];
    }
}

// ---------------- aggregation: 4 nodes/block, cross-node pipelined staging ---
// Double-buffered staging: node k+1's srcs/a_s loads are issued BEFORE node
// k's gather and stored to buffer (k+1)&1 after it; the epilogue barriers
// publish the stores. Hides the ~550-cycle staging chain per node.
__global__ void __launch_bounds__(128) aggregate_kernel(const float* __restrict__ bias,
                                                        const float* __restrict__ vdn,
                                                        float* __restrict__ out,
                                                        int mode) {
    __shared__ float s_ex[2][64][4];
    __shared__ int   s_si[2][64];
    __shared__ float sacc[4][256];
    __shared__ float sexs[4][4];
    __shared__ float s_adp[4][4];
    __shared__ float sh[256];
    __shared__ float s_red[2];

    const int nbase = blockIdx.x * NPB;
    const int tid = threadIdx.x;
    const int w = tid >> 5, lane = tid & 31;
    const int hsel = lane >> 3;
    const uint4* __restrict__ hs4u = (const uint4*)g_hsH;

    // prologue: stage node nbase, chunk 0, into buffer 0
    float4 ad_cur = make_float4(0.f, 0.f, 0.f, 0.f);
    if (tid < 64) {
        ad_cur = ((const float4*)g_ad)[nbase];
        int b0 = g_rowptr[nbase];
        int d0 = g_rowptr[nbase + 1] - b0;
        int m0 = d0 < 64 ? d0 : 64;
        if (tid < m0) {
            int sI = g_srcs[b0 + tid];
            float4 a = ((const float4*)g_as)[sI];
            *(float4*)s_ex[0][tid] = lrelu_exp4(a, ad_cur);
            s_si[0][tid] = sI;
        }
    }
    __syncthreads();

    for (int k = 0; k < NPB; k++) {
        const int n = nbase + k;
        const int base = g_rowptr[n];
        const int deg = g_rowptr[n + 1] - base;
        const int buf = k & 1;

        // prefetch next node's chunk-0 staging data (issued before gather)
        int   sI_nx = 0, m_nx = 0;
        float4 a_nx = make_float4(0.f, 0.f, 0.f, 0.f);
        float4 ad_nx = make_float4(0.f, 0.f, 0.f, 0.f);
        if (k < NPB - 1 && tid < 64) {
            int base_nx = g_rowptr[n + 1];
            int deg_nx = g_rowptr[n + 2] - base_nx;
            ad_nx = ((const float4*)g_ad)[n + 1];
            m_nx = deg_nx < 64 ? deg_nx : 64;
            if (tid < m_nx) {
                sI_nx = g_srcs[base_nx + tid];
                a_nx = ((const float4*)g_as)[sI_nx];
            }
        }

        float acc0 = 0.f, acc1 = 0.f, acc2 = 0.f, acc3 = 0.f;
        float acc4 = 0.f, acc5 = 0.f, acc6 = 0.f, acc7 = 0.f;
        float exs = 0.f;

#define EDGE_STEP(jj) do {                                        \
    float e = s_ex[buf][jj][hsel];                                \
    int s = s_si[buf][jj];                                        \
    uint4 hv = hs4u[(long)s * 32 + lane];                         \
    float2 f0 = __half22float2(*(__half2*)&hv.x);                 \
    float2 f1 = __half22float2(*(__half2*)&hv.y);                 \
    float2 f2 = __half22float2(*(__half2*)&hv.z);                 \
    float2 f3 = __half22float2(*(__half2*)&hv.w);                 \
    acc0 += e * f0.x; acc1 += e * f0.y;                           \
    acc2 += e * f1.x; acc3 += e * f1.y;                           \
    acc4 += e * f2.x; acc5 += e * f2.y;                           \
    acc6 += e * f3.x; acc7 += e * f3.y;                           \
    exs += e;                                                     \
} while (0)

        // gather chunk 0 (already staged)
        {
            int m = deg < 64 ? deg : 64;
            int j = w;
            for (; j + 28 < m; j += 32) {
                EDGE_STEP(j);
                EDGE_STEP(j + 4);
                EDGE_STEP(j + 8);
                EDGE_STEP(j + 12);
                EDGE_STEP(j + 16);
                EDGE_STEP(j + 20);
                EDGE_STEP(j + 24);
                EDGE_STEP(j + 28);
            }
            for (; j < m; j += 4) EDGE_STEP(j);
        }
        // rare spill chunks (deg > 64): stage into the current (dead-after) buffer
        for (int cs = 64; cs < deg; cs += 64) {
            __syncthreads();
            int mm = deg - cs; if (mm > 64) mm = 64;
            if (tid < mm) {
                int sI = g_srcs[base + cs + tid];
                float4 a = ((const float4*)g_as)[sI];
                *(float4*)s_ex[buf][tid] = lrelu_exp4(a, ad_cur);
                s_si[buf][tid] = sI;
            }
            __syncthreads();
            int j = w;
            for (; j < mm; j += 4) EDGE_STEP(j);
        }

        // store the prefetched staging data for node n+1 into the other buffer
        if (k < NPB - 1 && tid < m_nx) {
            *(float4*)s_ex[buf ^ 1][tid] = lrelu_exp4(a_nx, ad_nx);
            s_si[buf ^ 1][tid] = sI_nx;
        }
        ad_cur = ad_nx;

        // combine partials across warps (syncthreads also publish staging)
        __syncthreads();
        *(float4*)&sacc[w][lane * 8]     = make_float4(acc0, acc1, acc2, acc3);
        *(float4*)&sacc[w][lane * 8 + 4] = make_float4(acc4, acc5, acc6, acc7);
        if ((lane & 7) == 0) sexs[w][hsel] = exs;
        __syncthreads();

        float v0 = sacc[0][tid * 2] + sacc[1][tid * 2] + sacc[2][tid * 2] + sacc[3][tid * 2];
        float v1 = sacc[0][tid * 2 + 1] + sacc[1][tid * 2 + 1]
                 + sacc[2][tid * 2 + 1] + sacc[3][tid * 2 + 1];
        const float den = sexs[0][w] + sexs[1][w] + sexs[2][w] + sexs[3][w] + 1e-16f;
        v0 /= den;
        v1 /= den;

        const int col0 = tid * 2;
        if (mode == 0) {
            v0 += bias[col0];
            v1 += bias[col0 + 1];
            v0 = v0 > 0.f ? v0 : expm1f(v0);
            v1 = v1 > 0.f ? v1 : expm1f(v1);
            g_Af[(long)n * 128 + tid] = __floats2half2_rn(v0, v1);
            const float* p0 = &vdn[col0 * 4];
            float q0 = v0 * p0[0] + v1 * p0[4];
            float q1 = v0 * p0[1] + v1 * p0[5];
            float q2 = v0 * p0[2] + v1 * p0[6];
            float q3 = v0 * p0[3] + v1 * p0[7];
#pragma unroll
            for (int off = 16; off > 0; off >>= 1) {
                q0 += __shfl_xor_sync(0xffffffffu, q0, off);
                q1 += __shfl_xor_sync(0xffffffffu, q1, off);
                q2 += __shfl_xor_sync(0xffffffffu, q2, off);
                q3 += __shfl_xor_sync(0xffffffffu, q3, off);
            }
            if (lane < 4) {
                float q = lane == 0 ? q0 : lane == 1 ? q1 : lane == 2 ? q2 : q3;
                s_adp[w][lane] = q;
            }
            __syncthreads();
            if (tid < 4)
                g_ad[n * 4 + tid] = s_adp[0][tid] + s_adp[1][tid] + s_adp[2][tid] + s_adp[3][tid];
            __syncthreads();
        } else {
            sh[col0] = v0;
            sh[col0 + 1] = v1;
            __syncthreads();
            if (tid < 64)
                sh[tid] = 0.25f * (sh[tid] + sh[tid + 64] + sh[tid + 128] + sh[tid + 192]) + bias[tid];
            __syncthreads();
            if (tid < 32) {
                float a = fmaxf(sh[tid], sh[tid + 32]);
#pragma unroll
                for (int off = 16; off > 0; off >>= 1)
                    a = fmaxf(a, __shfl_xor_sync(0xffffffffu, a, off));
                if (tid == 0) s_red[0] = a;
            }
            __syncthreads();
            if (tid < 32) {
                float mx = s_red[0];
                float a = expf(sh[tid] - mx) + expf(sh[tid + 32] - mx);
#pragma unroll
                for (int off = 16; off > 0; off >>= 1)
                    a += __shfl_xor_sync(0xffffffffu, a, off);
                if (tid == 0) s_red[1] = a;
            }
            __syncthreads();
            if (tid < 64) out[(long)n * 64 + tid] = sh[tid] - s_red[0] - logf(s_red[1]);
            __syncthreads();
        }
    }
}

// ---------------- launch: R12 topology (CSR forked onto a side stream) -------
extern "C" void kernel_launch(void* const* d_in, const int* in_sizes, int n_in,
                              void* d_out, int out_size) {
    const float* x = (const float*)d_in[0];
    const int* ei = (const int*)d_in[1];
    int e2 = in_sizes[1] / 2;
    const int* src = ei;
    const int* dstp = ei + e2;
    const float* Ws[3] = {(const float*)d_in[2], (const float*)d_in[7],  (const float*)d_in[12]};
    const float* Wd[3] = {(const float*)d_in[3], (const float*)d_in[8],  (const float*)d_in[13]};
    const float* As[3] = {(const float*)d_in[4], (const float*)d_in[9],  (const float*)d_in[14]};
    const float* Ad[3] = {(const float*)d_in[5], (const float*)d_in[10], (const float*)d_in[15]};
    const float* Bb[3] = {(const float*)d_in[6], (const float*)d_in[11], (const float*)d_in[16]};
    float* out = (float*)d_out;

    float* vdPtr = 0;      cudaGetSymbolAddress((void**)&vdPtr, g_vd);
    __half* btPtr = 0;     cudaGetSymbolAddress((void**)&btPtr, g_Bt);
    int* degPtr = 0;       cudaGetSymbolAddress((void**)&degPtr, g_deg);

    const int GEMM_SMEM = 2 * STAGE_W * 4;   // 40960 B
    cudaFuncSetAttribute(gemm_mma_kernel, cudaFuncAttributeMaxDynamicSharedMemorySize,
                         GEMM_SMEM);

    int gE = (e2 + 255) / 256;

    // Fork a side stream for the CSR chain (independent of prologue + gemm0).
    cudaStream_t s2;
    cudaStreamCreateWithFlags(&s2, cudaStreamNonBlocking);
    cudaEvent_t eFork, eJoin;
    cudaEventCreateWithFlags(&eFork, cudaEventDisableTiming);
    cudaEventCreateWithFlags(&eJoin, cudaEventDisableTiming);

    cudaEventRecord(eFork, 0);
    cudaStreamWaitEvent(s2, eFork, 0);

    // side stream: CSR build
    cudaMemsetAsync(degPtr, 0, NNODES * sizeof(int), s2);
    count_deg_kernel<<<gE, 256, 0, s2>>>(dstp, e2);
    scan_kernel<<<1, 1024, 0, s2>>>();
    scatter_kernel<<<gE, 256, 0, s2>>>(src, dstp, e2);
    cudaEventRecord(eJoin, s2);

    // main stream: prologue + layer-0 GEMM (no CSR dependence)
    btsplit_all_kernel<<<dim3(KD * KD / 256, 3), 256>>>(Ws[0], Ws[1], Ws[2]);
    compute_vd_all_kernel<<<3, 1024>>>(Wd[0], Wd[1], Wd[2], Ad[0], Ad[1], Ad[2]);
    prep_x_kernel<<<(NNODES + 7) / 8, 256>>>(x);
    gemm_mma_kernel<<<dim3(MPAD / 128, 2), 256, GEMM_SMEM>>>(As[0], btPtr);

    // join: aggregate needs the CSR
    cudaStreamWaitEvent(0, eJoin, 0);

    aggregate_kernel<<<NNODES / NPB, 128>>>(Bb[0], vdPtr + 1 * KD * HEADS, (float*)0, 0);
    for (int l = 1; l < 3; l++) {
        gemm_mma_kernel<<<dim3(MPAD / 128, 2), 256, GEMM_SMEM>>>(
            As[l], btPtr + (size_t)l * KD * KD);
        if (l < 2)
            aggregate_kernel<<<NNODES / NPB, 128>>>(Bb[l], vdPtr + (l + 1) * KD * HEADS,
                                                    (float*)0, 0);
        else
            aggregate_kernel<<<NNODES / NPB, 128>>>(Bb[l], vdPtr, out, 1);
    }
    // Not destroying s2/events: destruction during active graph capture would
    // invalidate the capture; handles are tiny host-side objects (~2 calls).
}

// round 16
// speedup vs baseline: 1.0448x; 1.0448x over previous
#include <cuda_runtime.h>
#include <cuda_bf16.h>
#include <cuda_fp16.h>
#include <math.h>
#include <stdint.h>

#define NNODES 50000
#define MPAD   50048      // 391 * 128
#define KD     256
#define HEADS  4
#define EMAX   1700000

// ---------------- device scratch --------------------------------------------
__device__ __half2         g_hsH[MPAD * KD / 2]; // source transform (fp16)
__device__ __half2         g_Af[MPAD * KD / 2];  // activations, plain fp16
__device__ __half          g_Bt[3 * KD * KD];    // W^T fp16, all layers
__device__ float           g_as[MPAD * HEADS];
__device__ float           g_ad[NNODES * HEADS];
__device__ float           g_vd[3 * KD * HEADS]; // Wd_l @ att_d_l, [l][k][h]
__device__ int             g_deg[NNODES];
__device__ int             g_rowptr[NNODES + 1];
__device__ int             g_cursor[NNODES];
__device__ int             g_srcs[EMAX];         // CSR-ordered SOURCE ids

// ---------------- helpers ----------------------------------------------------
__device__ __forceinline__ void mma_f16(float* c, const uint32_t* a, const uint32_t* b) {
    asm volatile(
        "mma.sync.aligned.m16n8k16.row.col.f32.f16.f16.f32 "
        "{%0,%1,%2,%3},{%4,%5,%6,%7},{%8,%9},{%0,%1,%2,%3};"
        : "+f"(c[0]), "+f"(c[1]), "+f"(c[2]), "+f"(c[3])
        : "r"(a[0]), "r"(a[1]), "r"(a[2]), "r"(a[3]), "r"(b[0]), "r"(b[1]));
}

#define CP_ASYNC16(dst_u32, src_ptr) \
    asm volatile("cp.async.cg.shared.global [%0], [%1], 16;" \
                 :: "r"(dst_u32), "l"(src_ptr))
#define CP_COMMIT() asm volatile("cp.async.commit_group;" ::: "memory")
#define CP_WAIT0()  asm volatile("cp.async.wait_group 0;" ::: "memory")

// ---------------- CSR build --------------------------------------------------
__global__ void count_deg_kernel(const int* __restrict__ dst, int e2) {
    int e = blockIdx.x * blockDim.x + threadIdx.x;
    if (e < e2) atomicAdd(&g_deg[dst[e]], 1);
}
__global__ void scan_kernel() {
    __shared__ int s[1024];
    int t = threadIdx.x;
    const int per = (NNODES + 1023) / 1024;
    int start = t * per;
    int end = start + per; if (end > NNODES) end = NNODES;
    int sum = 0;
    for (int i = start; i < end; i++) sum += g_deg[i];
    s[t] = sum;
    __syncthreads();
    for (int off = 1; off < 1024; off <<= 1) {
        int v = (t >= off) ? s[t - off] : 0;
        __syncthreads();
        s[t] += v;
        __syncthreads();
    }
    int run = (t > 0) ? s[t - 1] : 0;
    for (int i = start; i < end; i++) {
        int d = g_deg[i];
        g_rowptr[i] = run;
        g_cursor[i] = run;
        run += d;
    }
    if (t == 0) g_rowptr[NNODES] = s[1023];
}
__global__ void scatter_kernel(const int* __restrict__ src,
                               const int* __restrict__ dst, int e2) {
    int e = blockIdx.x * blockDim.x + threadIdx.x;
    if (e < e2) {
        int pos = atomicAdd(&g_cursor[dst[e]], 1);
        g_srcs[pos] = src[e];
    }
}

// ---------------- fused: x -> fp16 AND layer-0 a_d ---------------------------
__global__ void __launch_bounds__(256) prep_x_kernel(const float* __restrict__ X) {
    __shared__ float svd[KD * 4];
    int tid = threadIdx.x;
    for (int i = tid; i < KD * 4; i += 256) svd[i] = g_vd[i];
    __syncthreads();
    int warp = tid >> 5, lane = tid & 31;
    int n = blockIdx.x * 8 + warp;
    if (n >= NNODES) return;
    float a0 = 0.f, a1 = 0.f, a2 = 0.f, a3 = 0.f;
#pragma unroll
    for (int g4 = 0; g4 < 2; g4++) {
        int f4i = n * 64 + lane * 2 + g4;
        float4 xv = ((const float4*)X)[f4i];
        __half2 h01 = __floats2half2_rn(xv.x, xv.y);
        __half2 h23 = __floats2half2_rn(xv.z, xv.w);
        uint2 hp;
        hp.x = *reinterpret_cast<unsigned*>(&h01);
        hp.y = *reinterpret_cast<unsigned*>(&h23);
        ((uint2*)g_Af)[f4i] = hp;
        const float* p = &svd[(lane * 8 + g4 * 4) * 4];
        a0 += xv.x * p[0] + xv.y * p[4] + xv.z * p[8]  + xv.w * p[12];
        a1 += xv.x * p[1] + xv.y * p[5] + xv.z * p[9]  + xv.w * p[13];
        a2 += xv.x * p[2] + xv.y * p[6] + xv.z * p[10] + xv.w * p[14];
        a3 += xv.x * p[3] + xv.y * p[7] + xv.z * p[11] + xv.w * p[15];
    }
#pragma unroll
    for (int off = 16; off > 0; off >>= 1) {
        a0 += __shfl_xor_sync(0xffffffffu, a0, off);
        a1 += __shfl_xor_sync(0xffffffffu, a1, off);
        a2 += __shfl_xor_sync(0xffffffffu, a2, off);
        a3 += __shfl_xor_sync(0xffffffffu, a3, off);
    }
    if (lane == 0) ((float4*)g_ad)[n] = make_float4(a0, a1, a2, a3);
}

// ---------------- B transpose -> fp16, all 3 layers --------------------------
__global__ void btsplit_all_kernel(const float* __restrict__ W0,
                                   const float* __restrict__ W1,
                                   const float* __restrict__ W2) {
    int l = blockIdx.y;
    const float* W = (l == 0) ? W0 : (l == 1) ? W1 : W2;
    int i = blockIdx.x * blockDim.x + threadIdx.x;
    int n = i >> 8, k = i & 255;
    g_Bt[l * KD * KD + i] = __float2half_rn(W[k * KD + n]);
}

// ---------------- vd for all layers in one launch ----------------------------
__global__ void compute_vd_all_kernel(const float* __restrict__ Wd0,
                                      const float* __restrict__ Wd1,
                                      const float* __restrict__ Wd2,
                                      const float* __restrict__ ad0,
                                      const float* __restrict__ ad1,
                                      const float* __restrict__ ad2) {
    int l = blockIdx.x;
    const float* Wd = (l == 0) ? Wd0 : (l == 1) ? Wd1 : Wd2;
    const float* ad = (l == 0) ? ad0 : (l == 1) ? ad1 : ad2;
    int idx = threadIdx.x;
    int k = idx >> 2;
    int h = idx & 3;
    float s = 0.f;
#pragma unroll 8
    for (int c = 0; c < 64; c++) s += Wd[k * KD + h * 64 + c] * ad[h * 64 + c];
    g_vd[l * KD * HEADS + k * 4 + h] = s;
}

// ---------------- GEMM: full 128x256 tile per CTA (A loaded once) ------------
// grid (391), 256 threads (8 warps). Warp tile 64x64: wm=wid>>2, wn=wid&3.
// Warp wn covers cols [64wn,64wn+64) == head wn -> a_s epilogue is
// single-writer (no atomics).
#define S32 20
#define STAGE_W 7680        // words per stage: A 128*20 + B 256*20
__global__ void __launch_bounds__(256) gemm_mma_kernel(const float* __restrict__ attS,
                                                       const __half* __restrict__ Bh) {
    extern __shared__ uint32_t smem_u[];
    __shared__ float s_as[128][4];
    const int tid = threadIdx.x;
    const int wid = tid >> 5, lane = tid & 31;
    const int wm = wid >> 2, wn = wid & 3;
    const int row0 = blockIdx.x * 128;
    const int g8 = lane >> 2, tq = lane & 3;
    const uint32_t smem_b = (uint32_t)__cvta_generic_to_shared(smem_u);
    const __half* Af = (const __half*)g_Af;

    const int lr = tid >> 2;            // 0..63
    const int lc4 = tid & 3;
    float c[4][8][4];
#pragma unroll
    for (int mt = 0; mt < 4; mt++)
#pragma unroll
        for (int nt = 0; nt < 8; nt++)
#pragma unroll
            for (int j = 0; j < 4; j++) c[mt][nt][j] = 0.f;

#define LOAD_CHUNK(stg, cc) do {                                               \
    int k0 = (cc) * 32;                                                        \
    _Pragma("unroll")                                                          \
    for (int i = 0; i < 2; i++) {       /* A: 128 rows */                      \
        int r = lr + i * 64;                                                   \
        long ga = (long)(row0 + r) * KD + k0 + lc4 * 8;                        \
        uint32_t so = smem_b + ((stg) * STAGE_W + r * S32 + lc4 * 4) * 4;      \
        CP_ASYNC16(so, Af + ga);                                               \
    }                                                                          \
    _Pragma("unroll")                                                          \
    for (int i = 0; i < 4; i++) {       /* B: 256 rows */                      \
        int r = lr + i * 64;                                                   \
        long gb = (long)r * KD + k0 + lc4 * 8;                                 \
        uint32_t so = smem_b + ((stg) * STAGE_W + 2560 + r * S32 + lc4 * 4) * 4; \
        CP_ASYNC16(so, Bh + gb);                                               \
    }                                                                          \
} while (0)

    LOAD_CHUNK(0, 0);
    CP_COMMIT();

    for (int cch = 0; cch < 8; cch++) {
        const int stg = cch & 1;
        CP_WAIT0();
        __syncthreads();
        if (cch < 7) { LOAD_CHUNK(stg ^ 1, cch + 1); CP_COMMIT(); }
        const uint32_t* sA = smem_u + stg * STAGE_W;
        const uint32_t* sB = sA + 2560;
#pragma unroll
        for (int kk = 0; kk < 2; kk++) {
            const int kb = kk * 8;
            uint32_t ah[4][4], bh[8][2];
#pragma unroll
            for (int mt = 0; mt < 4; mt++) {
                int r = (wm * 64 + mt * 16 + g8) * S32 + kb + tq;
                int r8 = r + 8 * S32;
                ah[mt][0] = sA[r];     ah[mt][1] = sA[r8];
                ah[mt][2] = sA[r + 4]; ah[mt][3] = sA[r8 + 4];
            }
#pragma unroll
            for (int nt = 0; nt < 8; nt++) {
                int r = (wn * 64 + nt * 8 + g8) * S32 + kb + tq;
                bh[nt][0] = sB[r]; bh[nt][1] = sB[r + 4];
            }
#pragma unroll
            for (int mt = 0; mt < 4; mt++)
#pragma unroll
                for (int nt = 0; nt < 8; nt++)
                    mma_f16(c[mt][nt], ah[mt], bh[nt]);
        }
        __syncthreads();
    }

    // epilogue 1: fragments -> g_hsH (fp16); cols = wn*64 + nt*8 + tq*2
#pragma unroll
    for (int mt = 0; mt < 4; mt++) {
        int r = row0 + wm * 64 + mt * 16 + g8;
#pragma unroll
        for (int nt = 0; nt < 8; nt++) {
            int h2i = wn * 32 + nt * 4 + tq;
            g_hsH[(long)r * 128 + h2i]       = __floats2half2_rn(c[mt][nt][0], c[mt][nt][1]);
            g_hsH[(long)(r + 8) * 128 + h2i] = __floats2half2_rn(c[mt][nt][2], c[mt][nt][3]);
        }
    }
    // epilogue 2: a_s — warp (wm,wn) is the sole writer of its (row, head=wn)
    {
        float p0[4] = {0.f, 0.f, 0.f, 0.f};
        float p1[4] = {0.f, 0.f, 0.f, 0.f};
#pragma unroll
        for (int nt = 0; nt < 8; nt++) {
            int col = wn * 64 + nt * 8 + tq * 2;
            float a0 = attS[col], a1 = attS[col + 1];
#pragma unroll
            for (int mt = 0; mt < 4; mt++) {
                p0[mt] += c[mt][nt][0] * a0 + c[mt][nt][1] * a1;
                p1[mt] += c[mt][nt][2] * a0 + c[mt][nt][3] * a1;
            }
        }
#pragma unroll
        for (int mt = 0; mt < 4; mt++) {
            p0[mt] += __shfl_xor_sync(0xffffffffu, p0[mt], 1);
            p0[mt] += __shfl_xor_sync(0xffffffffu, p0[mt], 2);
            p1[mt] += __shfl_xor_sync(0xffffffffu, p1[mt], 1);
            p1[mt] += __shfl_xor_sync(0xffffffffu, p1[mt], 2);
            if (tq == 0) {
                int rl = wm * 64 + mt * 16 + g8;
                s_as[rl][wn] = p0[mt];
                s_as[rl + 8][wn] = p1[mt];
            }
        }
        __syncthreads();
        // 512 values, 256 threads -> 2 each (contiguous float2 stores)
        ((float2*)&g_as[row0 * 4])[tid] = ((const float2*)s_as)[tid];
    }
}

// ---------------- aggregation: R14 structure (warp-per-edge LDG.128) ---------
__global__ void __launch_bounds__(128) aggregate_kernel(const float* __restrict__ bias,
                                                        const float* __restrict__ vdn,
                                                        float* __restrict__ out,
                                                        int mode) {
    __shared__ float s_ex[64][4];
    __shared__ int   s_si[64];
    __shared__ float sacc[4][256];
    __shared__ float sexs[4][4];
    __shared__ float s_adp[4][4];
    __shared__ float sh[256];
    __shared__ float s_red[2];

    const int n = blockIdx.x;
    const int tid = threadIdx.x;
    const int w = tid >> 5, lane = tid & 31;
    const int hsel = lane >> 3;
    const int base = g_rowptr[n];
    const int deg = g_rowptr[n + 1] - base;

    float4 ad4 = make_float4(0.f, 0.f, 0.f, 0.f);
    if (tid < 64) ad4 = ((const float4*)g_ad)[n];

    const uint4* __restrict__ hs4u = (const uint4*)g_hsH;

    float acc0 = 0.f, acc1 = 0.f, acc2 = 0.f, acc3 = 0.f;
    float acc4 = 0.f, acc5 = 0.f, acc6 = 0.f, acc7 = 0.f;
    float exs = 0.f;

#define EDGE_STEP(jj) do {                                        \
    float e = s_ex[jj][hsel];                                     \
    int s = s_si[jj];                                             \
    uint4 hv = hs4u[(long)s * 32 + lane];                         \
    float2 f0 = __half22float2(*(__half2*)&hv.x);                 \
    float2 f1 = __half22float2(*(__half2*)&hv.y);                 \
    float2 f2 = __half22float2(*(__half2*)&hv.z);                 \
    float2 f3 = __half22float2(*(__half2*)&hv.w);                 \
    acc0 += e * f0.x; acc1 += e * f0.y;                           \
    acc2 += e * f1.x; acc3 += e * f1.y;                           \
    acc4 += e * f2.x; acc5 += e * f2.y;                           \
    acc6 += e * f3.x; acc7 += e * f3.y;                           \
    exs += e;                                                     \
} while (0)

    for (int cs = 0; cs < deg; cs += 64) {
        int m = deg - cs; if (m > 64) m = 64;
        if (tid < m) {
            int sI = g_srcs[base + cs + tid];
            float4 a = ((const float4*)g_as)[sI];
            float v; float4 ex;
            v = a.x + ad4.x; v = v > 0.f ? v : 0.2f * v; ex.x = __expf(v);
            v = a.y + ad4.y; v = v > 0.f ? v : 0.2f * v; ex.y = __expf(v);
            v = a.z + ad4.z; v = v > 0.f ? v : 0.2f * v; ex.z = __expf(v);
            v = a.w + ad4.w; v = v > 0.f ? v : 0.2f * v; ex.w = __expf(v);
            *(float4*)s_ex[tid] = ex;
            s_si[tid] = sI;
        }
        __syncthreads();
        int j = w;
        for (; j + 28 < m; j += 32) {
            EDGE_STEP(j);
            EDGE_STEP(j + 4);
            EDGE_STEP(j + 8);
            EDGE_STEP(j + 12);
            EDGE_STEP(j + 16);
            EDGE_STEP(j + 20);
            EDGE_STEP(j + 24);
            EDGE_STEP(j + 28);
        }
        for (; j < m; j += 4) EDGE_STEP(j);
        if (cs + 64 < deg) __syncthreads();
    }

    __syncthreads();
    *(float4*)&sacc[w][lane * 8]     = make_float4(acc0, acc1, acc2, acc3);
    *(float4*)&sacc[w][lane * 8 + 4] = make_float4(acc4, acc5, acc6, acc7);
    if ((lane & 7) == 0) sexs[w][hsel] = exs;
    __syncthreads();

    float v0 = sacc[0][tid * 2] + sacc[1][tid * 2] + sacc[2][tid * 2] + sacc[3][tid * 2];
    float v1 = sacc[0][tid * 2 + 1] + sacc[1][tid * 2 + 1]
             + sacc[2][tid * 2 + 1] + sacc[3][tid * 2 + 1];
    const float den = sexs[0][w] + sexs[1][w] + sexs[2][w] + sexs[3][w] + 1e-16f;
    v0 /= den;
    v1 /= den;

    const int col0 = tid * 2;
    if (mode == 0) {
        v0 += bias[col0];
        v1 += bias[col0 + 1];
        v0 = v0 > 0.f ? v0 : expm1f(v0);
        v1 = v1 > 0.f ? v1 : expm1f(v1);
        g_Af[(long)n * 128 + tid] = __floats2half2_rn(v0, v1);
        const float* p0 = &vdn[col0 * 4];
        float q0 = v0 * p0[0] + v1 * p0[4];
        float q1 = v0 * p0[1] + v1 * p0[5];
        float q2 = v0 * p0[2] + v1 * p0[6];
        float q3 = v0 * p0[3] + v1 * p0[7];
#pragma unroll
        for (int off = 16; off > 0; off >>= 1) {
            q0 += __shfl_xor_sync(0xffffffffu, q0, off);
            q1 += __shfl_xor_sync(0xffffffffu, q1, off);
            q2 += __shfl_xor_sync(0xffffffffu, q2, off);
            q3 += __shfl_xor_sync(0xffffffffu, q3, off);
        }
        if (lane < 4) {
            float q = lane == 0 ? q0 : lane == 1 ? q1 : lane == 2 ? q2 : q3;
            s_adp[w][lane] = q;
        }
        __syncthreads();
        if (tid < 4)
            g_ad[n * 4 + tid] = s_adp[0][tid] + s_adp[1][tid] + s_adp[2][tid] + s_adp[3][tid];
    } else {
        sh[col0] = v0;
        sh[col0 + 1] = v1;
        __syncthreads();
        if (tid < 64)
            sh[tid] = 0.25f * (sh[tid] + sh[tid + 64] + sh[tid + 128] + sh[tid + 192]) + bias[tid];
        __syncthreads();
        if (tid < 32) {
            float a = fmaxf(sh[tid], sh[tid + 32]);
#pragma unroll
            for (int off = 16; off > 0; off >>= 1)
                a = fmaxf(a, __shfl_xor_sync(0xffffffffu, a, off));
            if (tid == 0) s_red[0] = a;
        }
        __syncthreads();
        if (tid < 32) {
            float mx = s_red[0];
            float a = expf(sh[tid] - mx) + expf(sh[tid + 32] - mx);
#pragma unroll
            for (int off = 16; off > 0; off >>= 1)
                a += __shfl_xor_sync(0xffffffffu, a, off);
            if (tid == 0) s_red[1] = a;
        }
        __syncthreads();
        if (tid < 64) out[(long)n * 64 + tid] = sh[tid] - s_red[0] - logf(s_red[1]);
    }
}

// ---------------- launch: R12/R14 topology (CSR forked onto side stream) -----
extern "C" void kernel_launch(void* const* d_in, const int* in_sizes, int n_in,
                              void* d_out, int out_size) {
    const float* x = (const float*)d_in[0];
    const int* ei = (const int*)d_in[1];
    int e2 = in_sizes[1] / 2;
    const int* src = ei;
    const int* dstp = ei + e2;
    const float* Ws[3] = {(const float*)d_in[2], (const float*)d_in[7],  (const float*)d_in[12]};
    const float* Wd[3] = {(const float*)d_in[3], (const float*)d_in[8],  (const float*)d_in[13]};
    const float* As[3] = {(const float*)d_in[4], (const float*)d_in[9],  (const float*)d_in[14]};
    const float* Ad[3] = {(const float*)d_in[5], (const float*)d_in[10], (const float*)d_in[15]};
    const float* Bb[3] = {(const float*)d_in[6], (const float*)d_in[11], (const float*)d_in[16]};
    float* out = (float*)d_out;

    float* vdPtr = 0;      cudaGetSymbolAddress((void**)&vdPtr, g_vd);
    __half* btPtr = 0;     cudaGetSymbolAddress((void**)&btPtr, g_Bt);
    int* degPtr = 0;       cudaGetSymbolAddress((void**)&degPtr, g_deg);

    const int GEMM_SMEM = 2 * STAGE_W * 4;   // 61440 B
    cudaFuncSetAttribute(gemm_mma_kernel, cudaFuncAttributeMaxDynamicSharedMemorySize,
                         GEMM_SMEM);

    int gE = (e2 + 255) / 256;

    // Fork a side stream for the CSR chain (independent of prologue + gemm0).
    cudaStream_t s2;
    cudaStreamCreateWithFlags(&s2, cudaStreamNonBlocking);
    cudaEvent_t eFork, eJoin;
    cudaEventCreateWithFlags(&eFork, cudaEventDisableTiming);
    cudaEventCreateWithFlags(&eJoin, cudaEventDisableTiming);

    cudaEventRecord(eFork, 0);
    cudaStreamWaitEvent(s2, eFork, 0);

    // side stream: CSR build
    cudaMemsetAsync(degPtr, 0, NNODES * sizeof(int), s2);
    count_deg_kernel<<<gE, 256, 0, s2>>>(dstp, e2);
    scan_kernel<<<1, 1024, 0, s2>>>();
    scatter_kernel<<<gE, 256, 0, s2>>>(src, dstp, e2);
    cudaEventRecord(eJoin, s2);

    // main stream: prologue + layer-0 GEMM (no CSR dependence)
    btsplit_all_kernel<<<dim3(KD * KD / 256, 3), 256>>>(Ws[0], Ws[1], Ws[2]);
    compute_vd_all_kernel<<<3, 1024>>>(Wd[0], Wd[1], Wd[2], Ad[0], Ad[1], Ad[2]);
    prep_x_kernel<<<(NNODES + 7) / 8, 256>>>(x);
    gemm_mma_kernel<<<MPAD / 128, 256, GEMM_SMEM>>>(As[0], btPtr);

    // join: aggregate needs the CSR
    cudaStreamWaitEvent(0, eJoin, 0);

    aggregate_kernel<<<NNODES, 128>>>(Bb[0], vdPtr + 1 * KD * HEADS, (float*)0, 0);
    for (int l = 1; l < 3; l++) {
        gemm_mma_kernel<<<MPAD / 128, 256, GEMM_SMEM>>>(
            As[l], btPtr + (size_t)l * KD * KD);
        if (l < 2)
            aggregate_kernel<<<NNODES, 128>>>(Bb[l], vdPtr + (l + 1) * KD * HEADS,
                                              (float*)0, 0);
        else
            aggregate_kernel<<<NNODES, 128>>>(Bb[l], vdPtr, out, 1);
    }
    // Not destroying s2/events: destruction during active graph capture would
    // invalidate the capture; handles are tiny host-side objects (~2 calls).
}